// round 1
// baseline (speedup 1.0000x reference)
#include <cuda_runtime.h>
#include <cstdint>

// ---------------- problem constants ----------------
#define T_TOK 8192      // B*S tokens
#define H_DIM 2048
#define DFF   8192
#define NE    8
#define TOPK  2
#define CAP   8192      // max rows per expert (top-2 distinct -> <= T per expert)
#define NPAIR (T_TOK * TOPK)

// ---------------- scratch (device globals; no cudaMalloc allowed) ----------------
__device__ float g_hmid[(size_t)NPAIR * DFF];     // 512 MB: gelu(x@w1) rows, packed by expert
__device__ float g_yslot[(size_t)NPAIR * H_DIM];  // 128 MB: weight-scaled expert outputs per (token,slot)
__device__ int   g_list[NE * CAP];                // pair id (= token*2 + slot) per expert row
__device__ float g_wt[NPAIR];                     // routing weight per pair
__device__ int   g_counts[NE];
__device__ int   g_off[NE];

// ---------------- small helpers ----------------
__device__ __forceinline__ float fast_tanh(float v) {
    float r;
    asm("tanh.approx.f32 %0, %1;" : "=f"(r) : "f"(v));
    return r;
}
__device__ __forceinline__ float gelu_tanh(float v) {
    // jax.nn.gelu default (approximate=True)
    float u = 0.7978845608028654f * (v + 0.044715f * v * v * v);
    return 0.5f * v * (1.0f + fast_tanh(u));
}

// ---------------- kernels ----------------
__global__ void zero_counts_kernel() {
    if (threadIdx.x < NE) g_counts[threadIdx.x] = 0;
}

__global__ void router_kernel(const float* __restrict__ x,
                              const float* __restrict__ wg,
                              float* __restrict__ logits_out) {
    int t    = blockIdx.x * (blockDim.x >> 5) + (threadIdx.x >> 5);
    int lane = threadIdx.x & 31;
    if (t >= T_TOK) return;

    const float* xr = x + (size_t)t * H_DIM;
    float acc[NE];
#pragma unroll
    for (int e = 0; e < NE; e++) acc[e] = 0.0f;

    for (int h = lane; h < H_DIM; h += 32) {
        float xv = xr[h];
        const float4* w4 = reinterpret_cast<const float4*>(wg + (size_t)h * NE);
        float4 a = w4[0], b = w4[1];
        acc[0] += xv * a.x; acc[1] += xv * a.y; acc[2] += xv * a.z; acc[3] += xv * a.w;
        acc[4] += xv * b.x; acc[5] += xv * b.y; acc[6] += xv * b.z; acc[7] += xv * b.w;
    }
#pragma unroll
    for (int e = 0; e < NE; e++) {
#pragma unroll
        for (int o = 16; o > 0; o >>= 1)
            acc[e] += __shfl_xor_sync(0xffffffffu, acc[e], o);
    }

    if (lane == 0) {
        // logits out (pre-softmax, fp32)
#pragma unroll
        for (int e = 0; e < NE; e++) logits_out[(size_t)t * NE + e] = acc[e];

        // softmax probs
        float m = acc[0];
#pragma unroll
        for (int e = 1; e < NE; e++) m = fmaxf(m, acc[e]);
        float p[NE], s = 0.0f;
#pragma unroll
        for (int e = 0; e < NE; e++) { p[e] = expf(acc[e] - m); s += p[e]; }
        float inv = 1.0f / s;

        // top-2 (lowest index wins ties, matching lax.top_k)
        int i0 = 0;
#pragma unroll
        for (int e = 1; e < NE; e++) if (acc[e] > acc[i0]) i0 = e;
        int i1 = (i0 == 0) ? 1 : 0;
#pragma unroll
        for (int e = 0; e < NE; e++) if (e != i0 && acc[e] > acc[i1]) i1 = e;

        int p0 = t * 2, p1 = t * 2 + 1;
        g_wt[p0] = p[i0] * inv;
        g_wt[p1] = p[i1] * inv;
        int pos0 = atomicAdd(&g_counts[i0], 1);
        g_list[i0 * CAP + pos0] = p0;
        int pos1 = atomicAdd(&g_counts[i1], 1);
        g_list[i1 * CAP + pos1] = p1;
    }
}

__global__ void offsets_kernel() {
    if (threadIdx.x == 0) {
        int s = 0;
#pragma unroll
        for (int e = 0; e < NE; e++) { g_off[e] = s; s += g_counts[e]; }
    }
}

// ---------------- tiled fp32 GEMMs: 128x128x16, 256 thr, 8x8 microtile ----------------
#define BM 128
#define BN 128
#define BK 16
#define ASTR 132   // padded A stride (keeps float4 reads 16B aligned: 132*4 % 16 == 0)

// GEMM1: hmid[off+m, n] = gelu( x[tok(m), :] @ w1[e][:, n] )
__global__ __launch_bounds__(256) void gemm1_kernel(const float* __restrict__ x,
                                                    const float* __restrict__ w1) {
    int e   = blockIdx.z;
    int cnt = g_counts[e];
    int m0  = blockIdx.y * BM;
    if (m0 >= cnt) return;
    int n0  = blockIdx.x * BN;
    int off = g_off[e];
    const float* B = w1 + (size_t)e * H_DIM * DFF;  // [H][DFF] row-major
    int tid = threadIdx.x;

    __shared__ __align__(16) float As[BK * ASTR];
    __shared__ __align__(16) float Bs[BK * BN];
    __shared__ int rowtok[BM];

    if (tid < BM) {
        int m = m0 + tid;
        rowtok[tid] = (m < cnt) ? (g_list[e * CAP + m] >> 1) : -1;
    }
    __syncthreads();

    int tx = tid & 15, ty = tid >> 4;
    float acc[8][8];
#pragma unroll
    for (int i = 0; i < 8; i++)
#pragma unroll
        for (int j = 0; j < 8; j++) acc[i][j] = 0.0f;

    for (int kt = 0; kt < H_DIM; kt += BK) {
        // A tile (gathered rows, transposed in smem)
#pragma unroll
        for (int it = 0; it < 2; it++) {
            int f  = tid + it * 256;
            int m  = f >> 2;
            int k4 = (f & 3) << 2;
            int tok = rowtok[m];
            float4 v = make_float4(0.f, 0.f, 0.f, 0.f);
            if (tok >= 0)
                v = *reinterpret_cast<const float4*>(x + (size_t)tok * H_DIM + kt + k4);
            As[(k4 + 0) * ASTR + m] = v.x;
            As[(k4 + 1) * ASTR + m] = v.y;
            As[(k4 + 2) * ASTR + m] = v.z;
            As[(k4 + 3) * ASTR + m] = v.w;
        }
        // B tile
#pragma unroll
        for (int it = 0; it < 2; it++) {
            int f  = tid + it * 256;
            int kk = f >> 5;
            int n4 = (f & 31) << 2;
            float4 v = *reinterpret_cast<const float4*>(B + (size_t)(kt + kk) * DFF + n0 + n4);
            *reinterpret_cast<float4*>(&Bs[kk * BN + n4]) = v;
        }
        __syncthreads();

#pragma unroll
        for (int kk = 0; kk < BK; kk++) {
            float4 a0 = *reinterpret_cast<const float4*>(&As[kk * ASTR + ty * 8]);
            float4 a1 = *reinterpret_cast<const float4*>(&As[kk * ASTR + ty * 8 + 4]);
            float4 b0 = *reinterpret_cast<const float4*>(&Bs[kk * BN + tx * 8]);
            float4 b1 = *reinterpret_cast<const float4*>(&Bs[kk * BN + tx * 8 + 4]);
            float a[8] = {a0.x, a0.y, a0.z, a0.w, a1.x, a1.y, a1.z, a1.w};
            float b[8] = {b0.x, b0.y, b0.z, b0.w, b1.x, b1.y, b1.z, b1.w};
#pragma unroll
            for (int i = 0; i < 8; i++)
#pragma unroll
                for (int j = 0; j < 8; j++) acc[i][j] = fmaf(a[i], b[j], acc[i][j]);
        }
        __syncthreads();
    }

    // epilogue: gelu + store to hmid
#pragma unroll
    for (int i = 0; i < 8; i++) {
        int m = ty * 8 + i;
        if (m0 + m < cnt) {
            float* orow = g_hmid + (size_t)(off + m0 + m) * DFF + n0 + tx * 8;
            float4 v0, v1;
            v0.x = gelu_tanh(acc[i][0]); v0.y = gelu_tanh(acc[i][1]);
            v0.z = gelu_tanh(acc[i][2]); v0.w = gelu_tanh(acc[i][3]);
            v1.x = gelu_tanh(acc[i][4]); v1.y = gelu_tanh(acc[i][5]);
            v1.z = gelu_tanh(acc[i][6]); v1.w = gelu_tanh(acc[i][7]);
            *reinterpret_cast<float4*>(orow)     = v0;
            *reinterpret_cast<float4*>(orow + 4) = v1;
        }
    }
}

// GEMM2: yslot[p, n] = wt[p] * ( hmid[off+m, :] @ w2[e][:, n] )
__global__ __launch_bounds__(256) void gemm2_kernel(const float* __restrict__ w2) {
    int e   = blockIdx.z;
    int cnt = g_counts[e];
    int m0  = blockIdx.y * BM;
    if (m0 >= cnt) return;
    int n0  = blockIdx.x * BN;
    int off = g_off[e];
    const float* B = w2 + (size_t)e * DFF * H_DIM;  // [DFF][H] row-major
    int tid = threadIdx.x;

    __shared__ __align__(16) float As[BK * ASTR];
    __shared__ __align__(16) float Bs[BK * BN];
    __shared__ int   ps[BM];
    __shared__ float ws[BM];

    if (tid < BM) {
        int m = m0 + tid;
        if (m < cnt) {
            int p = g_list[e * CAP + m];
            ps[tid] = p;
            ws[tid] = g_wt[p];
        } else {
            ps[tid] = 0;
            ws[tid] = 0.0f;
        }
    }
    __syncthreads();

    int tx = tid & 15, ty = tid >> 4;
    float acc[8][8];
#pragma unroll
    for (int i = 0; i < 8; i++)
#pragma unroll
        for (int j = 0; j < 8; j++) acc[i][j] = 0.0f;

    for (int kt = 0; kt < DFF; kt += BK) {
        // A tile (contiguous hmid rows of this expert)
#pragma unroll
        for (int it = 0; it < 2; it++) {
            int f  = tid + it * 256;
            int m  = f >> 2;
            int k4 = (f & 3) << 2;
            float4 v = make_float4(0.f, 0.f, 0.f, 0.f);
            if (m0 + m < cnt)
                v = *reinterpret_cast<const float4*>(g_hmid + (size_t)(off + m0 + m) * DFF + kt + k4);
            As[(k4 + 0) * ASTR + m] = v.x;
            As[(k4 + 1) * ASTR + m] = v.y;
            As[(k4 + 2) * ASTR + m] = v.z;
            As[(k4 + 3) * ASTR + m] = v.w;
        }
        // B tile
#pragma unroll
        for (int it = 0; it < 2; it++) {
            int f  = tid + it * 256;
            int kk = f >> 5;
            int n4 = (f & 31) << 2;
            float4 v = *reinterpret_cast<const float4*>(B + (size_t)(kt + kk) * H_DIM + n0 + n4);
            *reinterpret_cast<float4*>(&Bs[kk * BN + n4]) = v;
        }
        __syncthreads();

#pragma unroll
        for (int kk = 0; kk < BK; kk++) {
            float4 a0 = *reinterpret_cast<const float4*>(&As[kk * ASTR + ty * 8]);
            float4 a1 = *reinterpret_cast<const float4*>(&As[kk * ASTR + ty * 8 + 4]);
            float4 b0 = *reinterpret_cast<const float4*>(&Bs[kk * BN + tx * 8]);
            float4 b1 = *reinterpret_cast<const float4*>(&Bs[kk * BN + tx * 8 + 4]);
            float a[8] = {a0.x, a0.y, a0.z, a0.w, a1.x, a1.y, a1.z, a1.w};
            float b[8] = {b0.x, b0.y, b0.z, b0.w, b1.x, b1.y, b1.z, b1.w};
#pragma unroll
            for (int i = 0; i < 8; i++)
#pragma unroll
                for (int j = 0; j < 8; j++) acc[i][j] = fmaf(a[i], b[j], acc[i][j]);
        }
        __syncthreads();
    }

    // epilogue: scale by routing weight, scatter to per-(token,slot) buffer
#pragma unroll
    for (int i = 0; i < 8; i++) {
        int m = ty * 8 + i;
        if (m0 + m < cnt) {
            int   p = ps[m];
            float w = ws[m];
            float* orow = g_yslot + (size_t)p * H_DIM + n0 + tx * 8;
            float4 v0, v1;
            v0.x = w * acc[i][0]; v0.y = w * acc[i][1];
            v0.z = w * acc[i][2]; v0.w = w * acc[i][3];
            v1.x = w * acc[i][4]; v1.y = w * acc[i][5];
            v1.z = w * acc[i][6]; v1.w = w * acc[i][7];
            *reinterpret_cast<float4*>(orow)     = v0;
            *reinterpret_cast<float4*>(orow + 4) = v1;
        }
    }
}

__global__ void combine_kernel(float* __restrict__ out) {
    size_t i = (size_t)blockIdx.x * blockDim.x + threadIdx.x;
    const size_t total = (size_t)T_TOK * (H_DIM / 4);
    if (i >= total) return;
    size_t t  = i / (H_DIM / 4);
    size_t h4 = i % (H_DIM / 4);
    const float4* ys = reinterpret_cast<const float4*>(g_yslot);
    float4 a = ys[(2 * t)     * (H_DIM / 4) + h4];
    float4 b = ys[(2 * t + 1) * (H_DIM / 4) + h4];
    float4 r = make_float4(a.x + b.x, a.y + b.y, a.z + b.z, a.w + b.w);
    reinterpret_cast<float4*>(out)[i] = r;
}

// ---------------- launch ----------------
extern "C" void kernel_launch(void* const* d_in, const int* in_sizes, int n_in,
                              void* d_out, int out_size) {
    const float* x  = (const float*)d_in[0];   // [4,2048,2048]
    const float* wg = (const float*)d_in[1];   // [2048,8]
    const float* w1 = (const float*)d_in[2];   // [8,2048,8192]
    const float* w2 = (const float*)d_in[3];   // [8,8192,2048]
    float* out    = (float*)d_out;                         // [T, H]
    float* logits = out + (size_t)T_TOK * H_DIM;           // [T, E]

    zero_counts_kernel<<<1, 32>>>();
    router_kernel<<<T_TOK / 8, 256>>>(x, wg, logits);
    offsets_kernel<<<1, 32>>>();

    dim3 g1(DFF / BN, CAP / BM, NE);
    gemm1_kernel<<<g1, 256>>>(x, w1);

    dim3 g2(H_DIM / BN, CAP / BM, NE);
    gemm2_kernel<<<g2, 256>>>(w2);

    combine_kernel<<<(T_TOK * (H_DIM / 4) + 255) / 256, 256>>>(out);
}

// round 2
// speedup vs baseline: 2.7723x; 2.7723x over previous
#include <cuda_runtime.h>
#include <cuda_bf16.h>
#include <cstdint>

// ---------------- problem constants ----------------
#define T_TOK 8192
#define H_DIM 2048
#define DFF   8192
#define NE    8
#define CAP   8192
#define NPAIR (T_TOK * 2)

// ---------------- scratch (device globals) ----------------
__device__ __nv_bfloat16 g_xh[(size_t)T_TOK * H_DIM];
__device__ __nv_bfloat16 g_xl[(size_t)T_TOK * H_DIM];
__device__ __nv_bfloat16 g_w1h[(size_t)NE * H_DIM * DFF];
__device__ __nv_bfloat16 g_w1l[(size_t)NE * H_DIM * DFF];
__device__ __nv_bfloat16 g_w2h[(size_t)NE * DFF * H_DIM];
__device__ __nv_bfloat16 g_w2l[(size_t)NE * DFF * H_DIM];
__device__ __nv_bfloat16 g_hh[(size_t)NPAIR * DFF];
__device__ __nv_bfloat16 g_hl[(size_t)NPAIR * DFF];
__device__ float g_yslot[(size_t)NPAIR * H_DIM];
__device__ int   g_list[NE * CAP];
__device__ float g_wt[NPAIR];
__device__ int   g_counts[NE];
__device__ int   g_off[NE];

// ---------------- helpers ----------------
__device__ __forceinline__ float fast_tanh(float v) {
    float r; asm("tanh.approx.f32 %0, %1;" : "=f"(r) : "f"(v)); return r;
}
__device__ __forceinline__ float gelu_tanh(float v) {
    float u = 0.7978845608028654f * (v + 0.044715f * v * v * v);
    return 0.5f * v * (1.0f + fast_tanh(u));
}
__device__ __forceinline__ uint32_t pack_bf2(__nv_bfloat16 a, __nv_bfloat16 b) {
    __nv_bfloat162 p = __halves2bfloat162(a, b);
    return *reinterpret_cast<uint32_t*>(&p);
}
__device__ __forceinline__ void split2(float v, __nv_bfloat16& h, __nv_bfloat16& l) {
    h = __float2bfloat16(v);
    l = __float2bfloat16(v - __bfloat162float(h));
}

__device__ __forceinline__ void cp16(void* dst, const void* src) {
    uint32_t d = (uint32_t)__cvta_generic_to_shared(dst);
    asm volatile("cp.async.cg.shared.global [%0], [%1], 16;" :: "r"(d), "l"(src));
}
__device__ __forceinline__ void cp_commit() { asm volatile("cp.async.commit_group;"); }
__device__ __forceinline__ void cp_wait1() { asm volatile("cp.async.wait_group 1;"); }
__device__ __forceinline__ void cp_wait0() { asm volatile("cp.async.wait_group 0;"); }

// ldmatrix A: 16x16 bf16 tile, row-major [m][k], base points at (row0,k0)
__device__ __forceinline__ void ldm_a(uint32_t* r, const __nv_bfloat16* base, int stride) {
    int lane = threadIdx.x & 31;
    const __nv_bfloat16* p = base + (lane & 15) * stride + ((lane >> 4) << 3);
    uint32_t a = (uint32_t)__cvta_generic_to_shared(p);
    asm volatile("ldmatrix.sync.aligned.m8n8.x4.shared.b16 {%0,%1,%2,%3}, [%4];"
                 : "=r"(r[0]), "=r"(r[1]), "=r"(r[2]), "=r"(r[3]) : "r"(a));
}
// ldmatrix B (trans): 16x16 region of [k][n] row-major -> b-frags for 2 n8 tiles
__device__ __forceinline__ void ldm_b(uint32_t* r, const __nv_bfloat16* base, int stride) {
    int lane = threadIdx.x & 31;
    const __nv_bfloat16* p = base + (lane & 15) * stride + ((lane >> 4) << 3);
    uint32_t a = (uint32_t)__cvta_generic_to_shared(p);
    asm volatile("ldmatrix.sync.aligned.m8n8.x4.trans.shared.b16 {%0,%1,%2,%3}, [%4];"
                 : "=r"(r[0]), "=r"(r[1]), "=r"(r[2]), "=r"(r[3]) : "r"(a));
}
__device__ __forceinline__ void mma_bf16(float* c, const uint32_t* a, uint32_t b0, uint32_t b1) {
    asm volatile("mma.sync.aligned.m16n8k16.row.col.f32.bf16.bf16.f32 "
                 "{%0,%1,%2,%3}, {%4,%5,%6,%7}, {%8,%9}, {%0,%1,%2,%3};"
                 : "+f"(c[0]), "+f"(c[1]), "+f"(c[2]), "+f"(c[3])
                 : "r"(a[0]), "r"(a[1]), "r"(a[2]), "r"(a[3]), "r"(b0), "r"(b1));
}

// ---------------- routing kernels ----------------
__global__ void zero_counts_kernel() {
    if (threadIdx.x < NE) g_counts[threadIdx.x] = 0;
}

__global__ void router_kernel(const float* __restrict__ x,
                              const float* __restrict__ wg,
                              float* __restrict__ logits_out) {
    int t = blockIdx.x * (blockDim.x >> 5) + (threadIdx.x >> 5);
    int lane = threadIdx.x & 31;
    if (t >= T_TOK) return;
    const float* xr = x + (size_t)t * H_DIM;
    float acc[NE];
#pragma unroll
    for (int e = 0; e < NE; e++) acc[e] = 0.0f;
    for (int h = lane; h < H_DIM; h += 32) {
        float xv = xr[h];
        const float4* w4 = reinterpret_cast<const float4*>(wg + (size_t)h * NE);
        float4 a = w4[0], b = w4[1];
        acc[0] += xv * a.x; acc[1] += xv * a.y; acc[2] += xv * a.z; acc[3] += xv * a.w;
        acc[4] += xv * b.x; acc[5] += xv * b.y; acc[6] += xv * b.z; acc[7] += xv * b.w;
    }
#pragma unroll
    for (int e = 0; e < NE; e++)
#pragma unroll
        for (int o = 16; o > 0; o >>= 1)
            acc[e] += __shfl_xor_sync(0xffffffffu, acc[e], o);
    if (lane == 0) {
#pragma unroll
        for (int e = 0; e < NE; e++) logits_out[(size_t)t * NE + e] = acc[e];
        float m = acc[0];
#pragma unroll
        for (int e = 1; e < NE; e++) m = fmaxf(m, acc[e]);
        float p[NE], s = 0.0f;
#pragma unroll
        for (int e = 0; e < NE; e++) { p[e] = expf(acc[e] - m); s += p[e]; }
        float inv = 1.0f / s;
        int i0 = 0;
#pragma unroll
        for (int e = 1; e < NE; e++) if (acc[e] > acc[i0]) i0 = e;
        int i1 = (i0 == 0) ? 1 : 0;
#pragma unroll
        for (int e = 0; e < NE; e++) if (e != i0 && acc[e] > acc[i1]) i1 = e;
        int p0 = t * 2, p1 = t * 2 + 1;
        g_wt[p0] = p[i0] * inv;
        g_wt[p1] = p[i1] * inv;
        int pos0 = atomicAdd(&g_counts[i0], 1);
        g_list[i0 * CAP + pos0] = p0;
        int pos1 = atomicAdd(&g_counts[i1], 1);
        g_list[i1 * CAP + pos1] = p1;
    }
}

__global__ void offsets_kernel() {
    if (threadIdx.x == 0) {
        int s = 0;
#pragma unroll
        for (int e = 0; e < NE; e++) { g_off[e] = s; s += g_counts[e]; }
    }
}

// ---------------- split (fp32 -> bf16 hi + lo) ----------------
__global__ void split_kernel(const float* __restrict__ s,
                             __nv_bfloat16* __restrict__ h,
                             __nv_bfloat16* __restrict__ l, size_t n4) {
    size_t i = (size_t)blockIdx.x * blockDim.x + threadIdx.x;
    if (i >= n4) return;
    float4 v = reinterpret_cast<const float4*>(s)[i];
    __nv_bfloat16 h0, l0, h1, l1, h2, l2, h3, l3;
    split2(v.x, h0, l0); split2(v.y, h1, l1);
    split2(v.z, h2, l2); split2(v.w, h3, l3);
    uint2 hv, lv;
    hv.x = pack_bf2(h0, h1); hv.y = pack_bf2(h2, h3);
    lv.x = pack_bf2(l0, l1); lv.y = pack_bf2(l2, l3);
    reinterpret_cast<uint2*>(h)[i] = hv;
    reinterpret_cast<uint2*>(l)[i] = lv;
}

// ---------------- tensor-core GEMMs ----------------
#define BM 128
#define BN 128
#define BK 32
#define ASTR 40    // bf16 elems per A row (32 + 8 pad) -> 80B, conflict-free ldmatrix
#define BSTR 136   // bf16 elems per B row (128 + 8 pad) -> 272B, conflict-free ldmatrix
#define A_ELE (BM * ASTR)          // 5120
#define B_ELE (BK * BSTR)          // 4352
#define STAGE_ELE (2 * A_ELE + 2 * B_ELE)  // Ah Al Bh Bl = 18944
#define SMEM_DYN_BYTES (2 * STAGE_ELE * 2) // 75776 B

// issue cp.async for one k-tile; A gathered via rowsrc[] (absolute bf16 row base indices)
__device__ __forceinline__ void issue_tile(
    __nv_bfloat16* st, const size_t* rowsrc,
    const __nv_bfloat16* Ah, const __nv_bfloat16* Al,
    const __nv_bfloat16* Bh, const __nv_bfloat16* Bl,
    size_t bbase, int kt, int ldb, int tid)
{
    __nv_bfloat16* sAh = st;
    __nv_bfloat16* sAl = st + A_ELE;
    __nv_bfloat16* sBh = st + 2 * A_ELE;
    __nv_bfloat16* sBl = st + 2 * A_ELE + B_ELE;
#pragma unroll
    for (int it = 0; it < 2; it++) {
        int f = tid + it * 256;
        int row = f >> 2, c8 = (f & 3) << 3;
        size_t src = rowsrc[row] + kt + c8;
        cp16(sAh + row * ASTR + c8, Ah + src);
        cp16(sAl + row * ASTR + c8, Al + src);
    }
#pragma unroll
    for (int it = 0; it < 2; it++) {
        int f = tid + it * 256;
        int row = f >> 4, c8 = (f & 15) << 3;
        size_t src = bbase + (size_t)(kt + row) * ldb + c8;
        cp16(sBh + row * BSTR + c8, Bh + src);
        cp16(sBl + row * BSTR + c8, Bl + src);
    }
}

// shared inner compute on one stage
__device__ __forceinline__ void compute_tile(const __nv_bfloat16* st, float acc[4][4][4],
                                             int wm, int wn)
{
    const __nv_bfloat16* sAh = st;
    const __nv_bfloat16* sAl = st + A_ELE;
    const __nv_bfloat16* sBh = st + 2 * A_ELE;
    const __nv_bfloat16* sBl = st + 2 * A_ELE + B_ELE;
#pragma unroll
    for (int kk = 0; kk < BK; kk += 16) {
        uint32_t ah[4][4], al[4][4];
#pragma unroll
        for (int mi = 0; mi < 4; mi++) {
            ldm_a(ah[mi], sAh + (wm + mi * 16) * ASTR + kk, ASTR);
            ldm_a(al[mi], sAl + (wm + mi * 16) * ASTR + kk, ASTR);
        }
#pragma unroll
        for (int nj = 0; nj < 2; nj++) {
            uint32_t bh[4], bl[4];
            ldm_b(bh, sBh + kk * BSTR + wn + nj * 16, BSTR);
            ldm_b(bl, sBl + kk * BSTR + wn + nj * 16, BSTR);
#pragma unroll
            for (int mi = 0; mi < 4; mi++) {
                float* c0 = acc[mi][nj * 2];
                float* c1 = acc[mi][nj * 2 + 1];
                mma_bf16(c0, ah[mi], bh[0], bh[1]);
                mma_bf16(c0, al[mi], bh[0], bh[1]);
                mma_bf16(c0, ah[mi], bl[0], bl[1]);
                mma_bf16(c1, ah[mi], bh[2], bh[3]);
                mma_bf16(c1, al[mi], bh[2], bh[3]);
                mma_bf16(c1, ah[mi], bl[2], bl[3]);
            }
        }
    }
}

// GEMM1: hmid(hi/lo)[off+m] = split(gelu( x[tok(m)] @ w1[e] ))
__global__ __launch_bounds__(256) void gemm1_kernel() {
    extern __shared__ __nv_bfloat16 dyn[];
    int e = blockIdx.z;
    int cnt = g_counts[e];
    int m0 = blockIdx.y * BM;
    if (m0 >= cnt) return;
    int n0 = blockIdx.x * BN;
    int off = g_off[e];
    int tid = threadIdx.x;

    __shared__ size_t rowsrc[BM];
    if (tid < BM) {
        int m = m0 + tid;
        int tok = (m < cnt) ? (g_list[e * CAP + m] >> 1) : 0;
        rowsrc[tid] = (size_t)tok * H_DIM;
    }
    __syncthreads();

    size_t bbase = (size_t)e * H_DIM * DFF + n0;
    const int KIT = H_DIM / BK;

    issue_tile(dyn, rowsrc, g_xh, g_xl, g_w1h, g_w1l, bbase, 0, DFF, tid);
    cp_commit();

    int lane = tid & 31, warp = tid >> 5;
    int wm = (warp >> 2) * 64, wn = (warp & 3) * 32;
    float acc[4][4][4];
#pragma unroll
    for (int i = 0; i < 4; i++)
#pragma unroll
        for (int j = 0; j < 4; j++)
#pragma unroll
            for (int k = 0; k < 4; k++) acc[i][j][k] = 0.0f;

    for (int ki = 0; ki < KIT; ki++) {
        if (ki + 1 < KIT) {
            issue_tile(dyn + ((ki + 1) & 1) * STAGE_ELE, rowsrc,
                       g_xh, g_xl, g_w1h, g_w1l, bbase, (ki + 1) * BK, DFF, tid);
            cp_commit();
            cp_wait1();
        } else {
            cp_wait0();
        }
        __syncthreads();
        compute_tile(dyn + (ki & 1) * STAGE_ELE, acc, wm, wn);
        __syncthreads();
    }

    // epilogue: gelu, split to bf16 hi/lo
    int lr = lane >> 2, q2 = (lane & 3) * 2;
#pragma unroll
    for (int mi = 0; mi < 4; mi++) {
#pragma unroll
        for (int ni = 0; ni < 4; ni++) {
            float* c = acc[mi][ni];
            int gc = n0 + wn + ni * 8 + q2;
#pragma unroll
            for (int half = 0; half < 2; half++) {
                int m = wm + mi * 16 + lr + half * 8;
                if (m0 + m < cnt) {
                    size_t orow = (size_t)(off + m0 + m) * DFF + gc;
                    float gv0 = gelu_tanh(c[half * 2]);
                    float gv1 = gelu_tanh(c[half * 2 + 1]);
                    __nv_bfloat16 h0, l0, h1, l1;
                    split2(gv0, h0, l0); split2(gv1, h1, l1);
                    *reinterpret_cast<uint32_t*>(&g_hh[orow]) = pack_bf2(h0, h1);
                    *reinterpret_cast<uint32_t*>(&g_hl[orow]) = pack_bf2(l0, l1);
                }
            }
        }
    }
}

// GEMM2: yslot[p] = wt[p] * ( hmid[off+m] @ w2[e] )
__global__ __launch_bounds__(256) void gemm2_kernel() {
    extern __shared__ __nv_bfloat16 dyn[];
    int e = blockIdx.z;
    int cnt = g_counts[e];
    int m0 = blockIdx.y * BM;
    if (m0 >= cnt) return;
    int n0 = blockIdx.x * BN;
    int off = g_off[e];
    int tid = threadIdx.x;

    __shared__ size_t rowsrc[BM];
    __shared__ int   ps[BM];
    __shared__ float ws[BM];
    if (tid < BM) {
        int m = m0 + tid;
        int mc = (m < cnt) ? m : (cnt - 1);
        rowsrc[tid] = (size_t)(off + mc) * DFF;
        if (m < cnt) {
            int p = g_list[e * CAP + m];
            ps[tid] = p; ws[tid] = g_wt[p];
        } else { ps[tid] = 0; ws[tid] = 0.0f; }
    }
    __syncthreads();

    size_t bbase = (size_t)e * DFF * H_DIM + n0;
    const int KIT = DFF / BK;

    issue_tile(dyn, rowsrc, g_hh, g_hl, g_w2h, g_w2l, bbase, 0, H_DIM, tid);
    cp_commit();

    int lane = tid & 31, warp = tid >> 5;
    int wm = (warp >> 2) * 64, wn = (warp & 3) * 32;
    float acc[4][4][4];
#pragma unroll
    for (int i = 0; i < 4; i++)
#pragma unroll
        for (int j = 0; j < 4; j++)
#pragma unroll
            for (int k = 0; k < 4; k++) acc[i][j][k] = 0.0f;

    for (int ki = 0; ki < KIT; ki++) {
        if (ki + 1 < KIT) {
            issue_tile(dyn + ((ki + 1) & 1) * STAGE_ELE, rowsrc,
                       g_hh, g_hl, g_w2h, g_w2l, bbase, (ki + 1) * BK, H_DIM, tid);
            cp_commit();
            cp_wait1();
        } else {
            cp_wait0();
        }
        __syncthreads();
        compute_tile(dyn + (ki & 1) * STAGE_ELE, acc, wm, wn);
        __syncthreads();
    }

    int lr = lane >> 2, q2 = (lane & 3) * 2;
#pragma unroll
    for (int mi = 0; mi < 4; mi++) {
#pragma unroll
        for (int ni = 0; ni < 4; ni++) {
            float* c = acc[mi][ni];
            int gc = n0 + wn + ni * 8 + q2;
#pragma unroll
            for (int half = 0; half < 2; half++) {
                int m = wm + mi * 16 + lr + half * 8;
                if (m0 + m < cnt) {
                    int p = ps[m]; float w = ws[m];
                    float2 v = make_float2(w * c[half * 2], w * c[half * 2 + 1]);
                    *reinterpret_cast<float2*>(&g_yslot[(size_t)p * H_DIM + gc]) = v;
                }
            }
        }
    }
}

__global__ void combine_kernel(float* __restrict__ out) {
    size_t i = (size_t)blockIdx.x * blockDim.x + threadIdx.x;
    const size_t total = (size_t)T_TOK * (H_DIM / 4);
    if (i >= total) return;
    size_t t = i / (H_DIM / 4);
    size_t h4 = i % (H_DIM / 4);
    const float4* ys = reinterpret_cast<const float4*>(g_yslot);
    float4 a = ys[(2 * t) * (H_DIM / 4) + h4];
    float4 b = ys[(2 * t + 1) * (H_DIM / 4) + h4];
    reinterpret_cast<float4*>(out)[i] =
        make_float4(a.x + b.x, a.y + b.y, a.z + b.z, a.w + b.w);
}

// ---------------- launch ----------------
extern "C" void kernel_launch(void* const* d_in, const int* in_sizes, int n_in,
                              void* d_out, int out_size) {
    const float* x  = (const float*)d_in[0];
    const float* wg = (const float*)d_in[1];
    const float* w1 = (const float*)d_in[2];
    const float* w2 = (const float*)d_in[3];
    float* out    = (float*)d_out;
    float* logits = out + (size_t)T_TOK * H_DIM;

    static bool attr_done = false;
    if (!attr_done) {
        cudaFuncSetAttribute(gemm1_kernel, cudaFuncAttributeMaxDynamicSharedMemorySize, SMEM_DYN_BYTES);
        cudaFuncSetAttribute(gemm2_kernel, cudaFuncAttributeMaxDynamicSharedMemorySize, SMEM_DYN_BYTES);
        attr_done = true;
    }

    zero_counts_kernel<<<1, 32>>>();
    router_kernel<<<T_TOK / 8, 256>>>(x, logits ? wg : wg, logits);
    offsets_kernel<<<1, 32>>>();

    // splits
    {
        size_t n4x = (size_t)T_TOK * H_DIM / 4;
        __nv_bfloat16 *xh, *xl, *w1h, *w1l, *w2h, *w2l;
        cudaGetSymbolAddress((void**)&xh, g_xh);
        cudaGetSymbolAddress((void**)&xl, g_xl);
        cudaGetSymbolAddress((void**)&w1h, g_w1h);
        cudaGetSymbolAddress((void**)&w1l, g_w1l);
        cudaGetSymbolAddress((void**)&w2h, g_w2h);
        cudaGetSymbolAddress((void**)&w2l, g_w2l);
        split_kernel<<<(unsigned)((n4x + 255) / 256), 256>>>(x, xh, xl, n4x);
        size_t n4w = (size_t)NE * H_DIM * DFF / 4;
        split_kernel<<<(unsigned)((n4w + 255) / 256), 256>>>(w1, w1h, w1l, n4w);
        split_kernel<<<(unsigned)((n4w + 255) / 256), 256>>>(w2, w2h, w2l, n4w);
    }

    dim3 g1(DFF / BN, CAP / BM, NE);
    gemm1_kernel<<<g1, 256, SMEM_DYN_BYTES>>>();

    dim3 g2(H_DIM / BN, CAP / BM, NE);
    gemm2_kernel<<<g2, 256, SMEM_DYN_BYTES>>>();

    combine_kernel<<<(T_TOK * (H_DIM / 4) + 255) / 256, 256>>>(out);
}

// round 4
// speedup vs baseline: 5.9495x; 2.1460x over previous
#include <cuda_runtime.h>
#include <cuda_bf16.h>
#include <cstdint>

// tcgen05 is arch-specific: only emit it in the sm_103a/sm_100a pass.
// The compute_103 family pass compiles stubs (never selected at runtime —
// the exact-match sm_103a cubin wins).
#if defined(__CUDA_ARCH_FEAT_SM103_ALL) || defined(__CUDA_ARCH_FEAT_SM100_ALL) || defined(__CUDA_ARCH_FEAT_SM101_ALL)
#define TC_OK 1
#else
#define TC_OK 0
#endif

// ---------------- problem constants ----------------
#define T_TOK 8192
#define H_DIM 2048
#define DFF   8192
#define NE    8
#define CAP   8192
#define NPAIR (T_TOK * 2)

// ---------------- scratch (device globals) ----------------
__device__ __nv_bfloat16 g_xh[(size_t)T_TOK * H_DIM];
__device__ __nv_bfloat16 g_xl[(size_t)T_TOK * H_DIM];
// transposed weights: w1t [e][n=DFF][k=H], w2t [e][n=H][k=DFF], K-major rows
__device__ __nv_bfloat16 g_w1th[(size_t)NE * DFF * H_DIM];
__device__ __nv_bfloat16 g_w1tl[(size_t)NE * DFF * H_DIM];
__device__ __nv_bfloat16 g_w2th[(size_t)NE * H_DIM * DFF];
__device__ __nv_bfloat16 g_w2tl[(size_t)NE * H_DIM * DFF];
__device__ __nv_bfloat16 g_hh[(size_t)NPAIR * DFF];
__device__ __nv_bfloat16 g_hl[(size_t)NPAIR * DFF];
__device__ float g_yslot[(size_t)NPAIR * H_DIM];
__device__ int   g_list[NE * CAP];
__device__ float g_wt[NPAIR];
__device__ int   g_counts[NE];
__device__ int   g_off[NE];

// ---------------- scalar helpers ----------------
__device__ __forceinline__ float fast_tanh(float v) {
    float r; asm("tanh.approx.f32 %0, %1;" : "=f"(r) : "f"(v)); return r;
}
__device__ __forceinline__ float gelu_tanh(float v) {
    float u = 0.7978845608028654f * (v + 0.044715f * v * v * v);
    return 0.5f * v * (1.0f + fast_tanh(u));
}
__device__ __forceinline__ uint32_t pack_bf2(__nv_bfloat16 a, __nv_bfloat16 b) {
    __nv_bfloat162 p = __halves2bfloat162(a, b);
    return *reinterpret_cast<uint32_t*>(&p);
}
__device__ __forceinline__ void split2(float v, __nv_bfloat16& h, __nv_bfloat16& l) {
    h = __float2bfloat16(v);
    l = __float2bfloat16(v - __bfloat162float(h));
}

// ---------------- family-safe PTX helpers ----------------
__device__ __forceinline__ void cp16(void* dst, const void* src) {
    uint32_t d = (uint32_t)__cvta_generic_to_shared(dst);
    asm volatile("cp.async.cg.shared.global [%0], [%1], 16;" :: "r"(d), "l"(src));
}
__device__ __forceinline__ void cp_commit() { asm volatile("cp.async.commit_group;"); }
__device__ __forceinline__ void cp_wait1() { asm volatile("cp.async.wait_group 1;"); }
__device__ __forceinline__ void cp_wait0() { asm volatile("cp.async.wait_group 0;"); }

__device__ __forceinline__ uint32_t elect_one() {
    uint32_t pred;
    asm volatile("{\n\t.reg .pred p;\n\telect.sync _|p, 0xFFFFFFFF;\n\t"
                 "selp.b32 %0, 1, 0, p;\n\t}" : "=r"(pred));
    return pred;
}
__device__ __forceinline__ void fence_proxy_async_cta() {
    asm volatile("fence.proxy.async.shared::cta;" ::: "memory");
}
__device__ __forceinline__ void mbar_init(uint32_t a, uint32_t cnt) {
    asm volatile("mbarrier.init.shared.b64 [%0], %1;" :: "r"(a), "r"(cnt) : "memory");
}
__device__ __forceinline__ void mbar_inval(uint32_t a) {
    asm volatile("mbarrier.inval.shared.b64 [%0];" :: "r"(a) : "memory");
}
__device__ __forceinline__ void mbar_wait(uint32_t a, uint32_t parity) {
    uint32_t done;
    asm volatile("{\n\t.reg .pred p;\n\t"
                 "mbarrier.try_wait.parity.acquire.cta.shared::cta.b64 p, [%1], %2;\n\t"
                 "selp.b32 %0, 1, 0, p;\n\t}"
                 : "=r"(done) : "r"(a), "r"(parity) : "memory");
    if (!done) {
        asm volatile("{\n\t.reg .pred P1;\n\t"
                     "W_%=:\n\t"
                     "mbarrier.try_wait.parity.acquire.cta.shared::cta.b64 P1, [%0], %1, 0x989680;\n\t"
                     "@P1 bra.uni D_%=;\n\t"
                     "bra.uni W_%=;\n\t"
                     "D_%=:\n\t}"
                     :: "r"(a), "r"(parity) : "memory");
    }
}

#define SW64(x) ((x) ^ (((x) >> 3) & 0x30))

// ---------------- routing kernels ----------------
__global__ void zero_counts_kernel() {
    if (threadIdx.x < NE) g_counts[threadIdx.x] = 0;
}

__global__ void router_kernel(const float* __restrict__ x,
                              const float* __restrict__ wg,
                              float* __restrict__ logits_out) {
    int t = blockIdx.x * (blockDim.x >> 5) + (threadIdx.x >> 5);
    int lane = threadIdx.x & 31;
    if (t >= T_TOK) return;
    const float* xr = x + (size_t)t * H_DIM;
    float acc[NE];
#pragma unroll
    for (int e = 0; e < NE; e++) acc[e] = 0.0f;
    for (int h = lane; h < H_DIM; h += 32) {
        float xv = xr[h];
        const float4* w4 = reinterpret_cast<const float4*>(wg + (size_t)h * NE);
        float4 a = w4[0], b = w4[1];
        acc[0] += xv * a.x; acc[1] += xv * a.y; acc[2] += xv * a.z; acc[3] += xv * a.w;
        acc[4] += xv * b.x; acc[5] += xv * b.y; acc[6] += xv * b.z; acc[7] += xv * b.w;
    }
#pragma unroll
    for (int e = 0; e < NE; e++)
#pragma unroll
        for (int o = 16; o > 0; o >>= 1)
            acc[e] += __shfl_xor_sync(0xffffffffu, acc[e], o);
    if (lane == 0) {
#pragma unroll
        for (int e = 0; e < NE; e++) logits_out[(size_t)t * NE + e] = acc[e];
        float m = acc[0];
#pragma unroll
        for (int e = 1; e < NE; e++) m = fmaxf(m, acc[e]);
        float p[NE], s = 0.0f;
#pragma unroll
        for (int e = 0; e < NE; e++) { p[e] = expf(acc[e] - m); s += p[e]; }
        float inv = 1.0f / s;
        int i0 = 0;
#pragma unroll
        for (int e = 1; e < NE; e++) if (acc[e] > acc[i0]) i0 = e;
        int i1 = (i0 == 0) ? 1 : 0;
#pragma unroll
        for (int e = 0; e < NE; e++) if (e != i0 && acc[e] > acc[i1]) i1 = e;
        int p0 = t * 2, p1 = t * 2 + 1;
        g_wt[p0] = p[i0] * inv;
        g_wt[p1] = p[i1] * inv;
        int pos0 = atomicAdd(&g_counts[i0], 1);
        g_list[i0 * CAP + pos0] = p0;
        int pos1 = atomicAdd(&g_counts[i1], 1);
        g_list[i1 * CAP + pos1] = p1;
    }
}

__global__ void offsets_kernel() {
    if (threadIdx.x == 0) {
        int s = 0;
#pragma unroll
        for (int e = 0; e < NE; e++) { g_off[e] = s; s += g_counts[e]; }
    }
}

// ---------------- split x (fp32 -> bf16 hi + lo, no transpose) ----------------
__global__ void split_kernel(const float* __restrict__ s,
                             __nv_bfloat16* __restrict__ h,
                             __nv_bfloat16* __restrict__ l, size_t n4) {
    size_t i = (size_t)blockIdx.x * blockDim.x + threadIdx.x;
    if (i >= n4) return;
    float4 v = reinterpret_cast<const float4*>(s)[i];
    __nv_bfloat16 h0, l0, h1, l1, h2, l2, h3, l3;
    split2(v.x, h0, l0); split2(v.y, h1, l1);
    split2(v.z, h2, l2); split2(v.w, h3, l3);
    uint2 hv, lv;
    hv.x = pack_bf2(h0, h1); hv.y = pack_bf2(h2, h3);
    lv.x = pack_bf2(l0, l1); lv.y = pack_bf2(l2, l3);
    reinterpret_cast<uint2*>(h)[i] = hv;
    reinterpret_cast<uint2*>(l)[i] = lv;
}

// ---------------- transpose + split: W[e][K][N] -> Wt(h/l)[e][N][K] ----------------
__global__ void transpose_split_kernel(const float* __restrict__ src,
                                       __nv_bfloat16* __restrict__ dh,
                                       __nv_bfloat16* __restrict__ dl,
                                       int K, int N) {
    __shared__ float tile[32][33];
    int e = blockIdx.z;
    const float* S = src + (size_t)e * K * N;
    int n0 = blockIdx.x * 32, k0 = blockIdx.y * 32;
#pragma unroll
    for (int i = threadIdx.y; i < 32; i += 8)
        tile[i][threadIdx.x] = S[(size_t)(k0 + i) * N + n0 + threadIdx.x];
    __syncthreads();
    __nv_bfloat16* Dh = dh + (size_t)e * K * N;
    __nv_bfloat16* Dl = dl + (size_t)e * K * N;
#pragma unroll
    for (int i = threadIdx.y; i < 32; i += 8) {
        float v = tile[threadIdx.x][i];   // = S[k0+tx][n0+i]
        __nv_bfloat16 h, l;
        split2(v, h, l);
        size_t o = (size_t)(n0 + i) * K + k0 + threadIdx.x;
        Dh[o] = h;
        Dl[o] = l;
    }
}

// ---------------- tcgen05 GEMM: tile 256x256, BK=32, SW64, 2-stage ----------------
#define TM 256
#define TN 256
#define TBK 32
#define TILE_BYTES 16384                 // 256 rows x 64B
#define STAGE_BYTES (4 * TILE_BYTES)     // Ah Al Bh Bl = 64KB
#define SMEM_DYN (2 * STAGE_BYTES)       // 128KB

#if TC_OK
// ---- tcgen05 helpers (sm_103a pass only) ----
__device__ __forceinline__ uint64_t sw64_desc(uint32_t addr) {
    uint64_t d = 0;
    d |= (uint64_t)((addr >> 4) & 0x3FFF);
    d |= (uint64_t)1  << 16;   // LBO = 1  (16B inner stride)
    d |= (uint64_t)32 << 32;   // SBO = 32 (512B = 8 rows x 64B)
    d |= (uint64_t)1  << 46;   // version = 1 (Blackwell)
    d |= (uint64_t)4  << 61;   // layout = SW64
    return d;
}

// idesc kind::f16: dtype F32, atype/btype BF16, M=128, N=256
#define IDESC_F16 ((8u << 24) | (32u << 17) | (1u << 10) | (1u << 7) | (1u << 4))

__device__ __forceinline__ void mma_f16_ss(uint32_t d, uint64_t ad, uint64_t bd,
                                           uint32_t en) {
    asm volatile(
        "{\n\t.reg .pred p;\n\tsetp.ne.u32 p, %4, 0;\n\t"
        "tcgen05.mma.cta_group::1.kind::f16 [%0], %1, %2, %3, {%5,%5,%5,%5}, p;\n\t}"
        :: "r"(d), "l"(ad), "l"(bd), "r"(IDESC_F16), "r"(en), "r"(0u) : "memory");
}
__device__ __forceinline__ void tc_alloc(uint32_t smem_slot, uint32_t ncols) {
    asm volatile("tcgen05.alloc.cta_group::1.sync.aligned.shared::cta.b32 [%0], %1;"
                 :: "r"(smem_slot), "r"(ncols) : "memory");
}
__device__ __forceinline__ void tc_relinquish() {
    asm volatile("tcgen05.relinquish_alloc_permit.cta_group::1.sync.aligned;");
}
__device__ __forceinline__ void tc_dealloc(uint32_t tmem, uint32_t ncols) {
    asm volatile("tcgen05.dealloc.cta_group::1.sync.aligned.b32 %0, %1;"
                 :: "r"(tmem), "r"(ncols));
}
__device__ __forceinline__ void tc_commit(uint32_t mbar) {
    asm volatile("tcgen05.commit.cta_group::1.mbarrier::arrive::one.shared::cluster.b64 [%0];"
                 :: "r"(mbar) : "memory");
}
__device__ __forceinline__ void tc_fence_after() {
    asm volatile("tcgen05.fence::after_thread_sync;" ::: "memory");
}
__device__ __forceinline__ void tmem_ld32(uint32_t* r, uint32_t addr) {
    asm volatile(
        "tcgen05.ld.sync.aligned.32x32b.x32.b32 "
        "{%0,%1,%2,%3,%4,%5,%6,%7,%8,%9,%10,%11,%12,%13,%14,%15,"
        "%16,%17,%18,%19,%20,%21,%22,%23,%24,%25,%26,%27,%28,%29,%30,%31}, [%32];"
        : "=r"(r[0]), "=r"(r[1]), "=r"(r[2]), "=r"(r[3]), "=r"(r[4]), "=r"(r[5]),
          "=r"(r[6]), "=r"(r[7]), "=r"(r[8]), "=r"(r[9]), "=r"(r[10]), "=r"(r[11]),
          "=r"(r[12]), "=r"(r[13]), "=r"(r[14]), "=r"(r[15]), "=r"(r[16]), "=r"(r[17]),
          "=r"(r[18]), "=r"(r[19]), "=r"(r[20]), "=r"(r[21]), "=r"(r[22]), "=r"(r[23]),
          "=r"(r[24]), "=r"(r[25]), "=r"(r[26]), "=r"(r[27]), "=r"(r[28]), "=r"(r[29]),
          "=r"(r[30]), "=r"(r[31])
        : "r"(addr));
}
__device__ __forceinline__ void tmem_wait_ld() {
    asm volatile("tcgen05.wait::ld.sync.aligned;" ::: "memory");
}

__device__ __forceinline__ void fill_stage(
    char* st, const size_t* rowsrc,
    const __nv_bfloat16* Ah, const __nv_bfloat16* Al,
    const __nv_bfloat16* Bh, const __nv_bfloat16* Bl,
    size_t bbase, size_t ldk, int kt, int tid)
{
    char* sAh = st;
    char* sAl = st + TILE_BYTES;
    char* sBh = st + 2 * TILE_BYTES;
    char* sBl = st + 3 * TILE_BYTES;
#pragma unroll
    for (int it = 0; it < 4; it++) {
        int f = tid + it * 256;
        int row = f >> 2, c = f & 3;
        uint32_t doff = SW64(row * 64 + c * 16);
        size_t asrc = rowsrc[row] + kt + c * 8;
        cp16(sAh + doff, Ah + asrc);
        cp16(sAl + doff, Al + asrc);
        size_t bsrc = bbase + (size_t)row * ldk + kt + c * 8;
        cp16(sBh + doff, Bh + bsrc);
        cp16(sBl + doff, Bl + bsrc);
    }
}

// fills + MMA loop; on return TMEM D [2 subtiles x 128 lanes x 256 cols] ready
__device__ __forceinline__ void run_mainloop(
    char* dyn, const size_t* rowsrc,
    const __nv_bfloat16* Ah, const __nv_bfloat16* Al,
    const __nv_bfloat16* Bh, const __nv_bfloat16* Bl,
    size_t bbase, size_t ldk, int KIT,
    uint32_t tmem_base, uint32_t mbar0, int tid)
{
    fill_stage(dyn, rowsrc, Ah, Al, Bh, Bl, bbase, ldk, 0, tid);
    cp_commit();
    fill_stage(dyn + STAGE_BYTES, rowsrc, Ah, Al, Bh, Bl, bbase, ldk, TBK, tid);
    cp_commit();

    uint32_t dynb = (uint32_t)__cvta_generic_to_shared(dyn);
    int ph0 = 0, ph1 = 0;

    for (int ki = 0; ki < KIT; ki++) {
        int s = ki & 1;
        if (ki + 1 < KIT) cp_wait1(); else cp_wait0();
        __syncthreads();
        if ((tid >> 5) == 0) {
            fence_proxy_async_cta();
            if (elect_one()) {
                uint32_t base = dynb + s * STAGE_BYTES;
                uint64_t dA  = sw64_desc(base);
                uint64_t dAl = sw64_desc(base + TILE_BYTES);
                uint64_t dBh = sw64_desc(base + 2 * TILE_BYTES);
                uint64_t dBl = sw64_desc(base + 3 * TILE_BYTES);
#pragma unroll
                for (int sub = 0; sub < 2; sub++) {
                    uint32_t d = tmem_base + sub * 256;
                    uint32_t aoff = sub * 512;   // +128 rows * 64B = 8192B = 512 units
#pragma unroll
                    for (int c = 0; c < 2; c++) {
                        uint32_t en0 = (ki > 0 || c > 0) ? 1u : 0u;
                        mma_f16_ss(d, dA  + aoff + c * 2, dBh + c * 2, en0);
                        mma_f16_ss(d, dAl + aoff + c * 2, dBh + c * 2, 1u);
                        mma_f16_ss(d, dA  + aoff + c * 2, dBl + c * 2, 1u);
                    }
                }
                tc_commit(mbar0 + s * 8);
            }
        }
        if (ki + 2 < KIT) {
            int phs = s ? ph1 : ph0;
            mbar_wait(mbar0 + s * 8, phs);
            if (s) ph1 ^= 1; else ph0 ^= 1;
            fill_stage(dyn + s * STAGE_BYTES, rowsrc, Ah, Al, Bh, Bl,
                       bbase, ldk, (ki + 2) * TBK, tid);
            cp_commit();
        }
    }
    int sl = (KIT - 1) & 1;
    mbar_wait(mbar0 + sl * 8, sl ? ph1 : ph0);
    tc_fence_after();
    __syncthreads();
}
#endif  // TC_OK

// GEMM1: hmid(hi/lo)[off+m] = split(gelu( x[tok(m)] @ w1t[e]^T ))
__global__ __launch_bounds__(256) void gemm1_kernel() {
#if TC_OK
    extern __shared__ __align__(1024) char dyn[];
    __shared__ __align__(16) unsigned long long mbars[2];
    __shared__ uint32_t tmem_slot;
    __shared__ size_t rowsrc[TM];

    int e = blockIdx.z;
    int cnt = g_counts[e];
    int m0 = blockIdx.y * TM;
    if (m0 >= cnt) return;
    int n0 = blockIdx.x * TN;
    int off = g_off[e];
    int tid = threadIdx.x;

    uint32_t mbar0 = (uint32_t)__cvta_generic_to_shared(&mbars[0]);
    uint32_t slot  = (uint32_t)__cvta_generic_to_shared(&tmem_slot);

    if ((tid >> 5) == 0) tc_alloc(slot, 512);
    if (tid == 0) { mbar_init(mbar0, 1); mbar_init(mbar0 + 8, 1); }
    if (tid < TM) {
        int m = m0 + tid;
        int tok = (m < cnt) ? (g_list[e * CAP + m] >> 1) : (g_list[e * CAP + cnt - 1] >> 1);
        rowsrc[tid] = (size_t)tok * H_DIM;
    }
    __syncthreads();
    if ((tid >> 5) == 0) tc_relinquish();
    uint32_t tmem_base = tmem_slot;

    size_t bbase = ((size_t)e * DFF + n0) * H_DIM;
    run_mainloop(dyn, rowsrc, g_xh, g_xl, g_w1th, g_w1tl,
                 bbase, H_DIM, H_DIM / TBK, tmem_base, mbar0, tid);

    // epilogue: gelu + split -> bf16 hi/lo hmid
    int w = tid >> 5, lane = tid & 31;
    int sub = w >> 2, pw = w & 3;
    int m = sub * 128 + pw * 32 + lane;
    bool ok = (m0 + m) < cnt;
    size_t orow = (size_t)(off + m0 + m) * DFF + n0;
#pragma unroll
    for (int cc = 0; cc < 8; cc++) {
        uint32_t r[32];
        tmem_ld32(r, tmem_base + sub * 256 + cc * 32);
        tmem_wait_ld();
        if (ok) {
            uint32_t hw[16], lw[16];
#pragma unroll
            for (int j = 0; j < 16; j++) {
                float f0 = gelu_tanh(__uint_as_float(r[2 * j]));
                float f1 = gelu_tanh(__uint_as_float(r[2 * j + 1]));
                __nv_bfloat16 h0, l0, h1, l1;
                split2(f0, h0, l0); split2(f1, h1, l1);
                hw[j] = pack_bf2(h0, h1);
                lw[j] = pack_bf2(l0, l1);
            }
            uint4* dh = reinterpret_cast<uint4*>(&g_hh[orow + cc * 32]);
            uint4* dl = reinterpret_cast<uint4*>(&g_hl[orow + cc * 32]);
#pragma unroll
            for (int q = 0; q < 4; q++) {
                dh[q] = make_uint4(hw[4 * q], hw[4 * q + 1], hw[4 * q + 2], hw[4 * q + 3]);
                dl[q] = make_uint4(lw[4 * q], lw[4 * q + 1], lw[4 * q + 2], lw[4 * q + 3]);
            }
        }
    }
    __syncthreads();
    if (tid == 0) { mbar_inval(mbar0); mbar_inval(mbar0 + 8); }
    __syncthreads();
    if ((tid >> 5) == 0) tc_dealloc(tmem_base, 512);
#endif
}

// GEMM2: yslot[p] = wt[p] * ( hmid[off+m] @ w2t[e]^T )
__global__ __launch_bounds__(256) void gemm2_kernel() {
#if TC_OK
    extern __shared__ __align__(1024) char dyn[];
    __shared__ __align__(16) unsigned long long mbars[2];
    __shared__ uint32_t tmem_slot;
    __shared__ size_t rowsrc[TM];
    __shared__ int   ps[TM];
    __shared__ float ws[TM];

    int e = blockIdx.z;
    int cnt = g_counts[e];
    int m0 = blockIdx.y * TM;
    if (m0 >= cnt) return;
    int n0 = blockIdx.x * TN;
    int off = g_off[e];
    int tid = threadIdx.x;

    uint32_t mbar0 = (uint32_t)__cvta_generic_to_shared(&mbars[0]);
    uint32_t slot  = (uint32_t)__cvta_generic_to_shared(&tmem_slot);

    if ((tid >> 5) == 0) tc_alloc(slot, 512);
    if (tid == 0) { mbar_init(mbar0, 1); mbar_init(mbar0 + 8, 1); }
    if (tid < TM) {
        int m = m0 + tid;
        int mc = (m < cnt) ? m : (cnt - 1);
        rowsrc[tid] = (size_t)(off + mc) * DFF;
        if (m < cnt) {
            int p = g_list[e * CAP + m];
            ps[tid] = p; ws[tid] = g_wt[p];
        } else { ps[tid] = 0; ws[tid] = 0.0f; }
    }
    __syncthreads();
    if ((tid >> 5) == 0) tc_relinquish();
    uint32_t tmem_base = tmem_slot;

    size_t bbase = ((size_t)e * H_DIM + n0) * DFF;
    run_mainloop(dyn, rowsrc, g_hh, g_hl, g_w2th, g_w2tl,
                 bbase, DFF, DFF / TBK, tmem_base, mbar0, tid);

    int w = tid >> 5, lane = tid & 31;
    int sub = w >> 2, pw = w & 3;
    int m = sub * 128 + pw * 32 + lane;
    bool ok = (m0 + m) < cnt;
    int   pp = ps[m];
    float wv = ws[m];
    float* orow = g_yslot + (size_t)pp * H_DIM + n0;
#pragma unroll
    for (int cc = 0; cc < 8; cc++) {
        uint32_t r[32];
        tmem_ld32(r, tmem_base + sub * 256 + cc * 32);
        tmem_wait_ld();
        if (ok) {
            float4* dst = reinterpret_cast<float4*>(orow + cc * 32);
#pragma unroll
            for (int q = 0; q < 8; q++) {
                dst[q] = make_float4(wv * __uint_as_float(r[4 * q]),
                                     wv * __uint_as_float(r[4 * q + 1]),
                                     wv * __uint_as_float(r[4 * q + 2]),
                                     wv * __uint_as_float(r[4 * q + 3]));
            }
        }
    }
    __syncthreads();
    if (tid == 0) { mbar_inval(mbar0); mbar_inval(mbar0 + 8); }
    __syncthreads();
    if ((tid >> 5) == 0) tc_dealloc(tmem_base, 512);
#endif
}

__global__ void combine_kernel(float* __restrict__ out) {
    size_t i = (size_t)blockIdx.x * blockDim.x + threadIdx.x;
    const size_t total = (size_t)T_TOK * (H_DIM / 4);
    if (i >= total) return;
    size_t t = i / (H_DIM / 4);
    size_t h4 = i % (H_DIM / 4);
    const float4* ys = reinterpret_cast<const float4*>(g_yslot);
    float4 a = ys[(2 * t) * (H_DIM / 4) + h4];
    float4 b = ys[(2 * t + 1) * (H_DIM / 4) + h4];
    reinterpret_cast<float4*>(out)[i] =
        make_float4(a.x + b.x, a.y + b.y, a.z + b.z, a.w + b.w);
}

// ---------------- launch ----------------
extern "C" void kernel_launch(void* const* d_in, const int* in_sizes, int n_in,
                              void* d_out, int out_size) {
    const float* x  = (const float*)d_in[0];
    const float* wg = (const float*)d_in[1];
    const float* w1 = (const float*)d_in[2];
    const float* w2 = (const float*)d_in[3];
    float* out    = (float*)d_out;
    float* logits = out + (size_t)T_TOK * H_DIM;

    static bool attr_done = false;
    if (!attr_done) {
        cudaFuncSetAttribute(gemm1_kernel, cudaFuncAttributeMaxDynamicSharedMemorySize, SMEM_DYN);
        cudaFuncSetAttribute(gemm2_kernel, cudaFuncAttributeMaxDynamicSharedMemorySize, SMEM_DYN);
        attr_done = true;
    }

    zero_counts_kernel<<<1, 32>>>();
    router_kernel<<<T_TOK / 8, 256>>>(x, wg, logits);
    offsets_kernel<<<1, 32>>>();

    {
        __nv_bfloat16 *xh, *xl, *w1th, *w1tl, *w2th, *w2tl;
        cudaGetSymbolAddress((void**)&xh,  g_xh);
        cudaGetSymbolAddress((void**)&xl,  g_xl);
        cudaGetSymbolAddress((void**)&w1th, g_w1th);
        cudaGetSymbolAddress((void**)&w1tl, g_w1tl);
        cudaGetSymbolAddress((void**)&w2th, g_w2th);
        cudaGetSymbolAddress((void**)&w2tl, g_w2tl);

        size_t n4x = (size_t)T_TOK * H_DIM / 4;
        split_kernel<<<(unsigned)((n4x + 255) / 256), 256>>>(x, xh, xl, n4x);

        dim3 bt(32, 8);
        dim3 gt1(DFF / 32, H_DIM / 32, NE);   // w1: K=H_DIM, N=DFF
        transpose_split_kernel<<<gt1, bt>>>(w1, w1th, w1tl, H_DIM, DFF);
        dim3 gt2(H_DIM / 32, DFF / 32, NE);   // w2: K=DFF, N=H_DIM
        transpose_split_kernel<<<gt2, bt>>>(w2, w2th, w2tl, DFF, H_DIM);
    }

    dim3 g1(DFF / TN, CAP / TM, NE);
    gemm1_kernel<<<g1, 256, SMEM_DYN>>>();

    dim3 g2(H_DIM / TN, CAP / TM, NE);
    gemm2_kernel<<<g2, 256, SMEM_DYN>>>();

    combine_kernel<<<(T_TOK * (H_DIM / 4) + 255) / 256, 256>>>(out);
}